// round 4
// baseline (speedup 1.0000x reference)
#include <cuda_runtime.h>
#include <cuda_bf16.h>

#define N_NODES 50000
#define N_EDGES 1250000
#define HID 64
#define CDIM 128
#define NTILE 32                                     // nodes per block-tile
#define N_TILES ((N_NODES + NTILE - 1) / NTILE)      // 1563
#define SCAT_BLOCKS 444
#define GEMM_BLOCKS 148
#define TOTAL_BLOCKS (SCAT_BLOCKS + GEMM_BLOCKS)
#define TOTAL_ITEMS (16LL * N_EDGES)                 // 20M (edge, float4-group) items
#define SPLIT_ITEMS 17500000LL                       // 16- and 32-aligned

// scratch: t1 = x @ W1[0:64] + b1
__device__ float d_t1[(size_t)N_NODES * HID];

// ---------------------------------------------------------------------------
// scatter work: sequential edge_attr stream + vector reductions into L2.
// Warp covers 32 consecutive items = 2 edges x 16 float4-groups.
//  - g = idx & 15 is loop-invariant (strides are multiples of 16)
//  - row[e] loaded by lanes 0/16 only, shfl-broadcast (cuts LSU lanes ~31%)
// Requires: beg, idx0-base, stride all multiples of 32 at warp granularity.
// ---------------------------------------------------------------------------
__device__ __forceinline__ void scatter_range(const int* __restrict__ row,
                                              const float4* __restrict__ attr4,
                                              float* __restrict__ combined,
                                              long long beg, long long end,
                                              long long idx0, long long stride) {
    int lane = threadIdx.x & 31;
    int g = (int)((beg + idx0) & 15);        // loop-invariant
    long long idx = beg + idx0;

    // main: full-warp iterations (all 32 lanes in range)
    while (idx - lane + 31 < end) {
        int e = (int)(idx >> 4);
        int r;
        if ((lane & 15) == 0) r = __ldg(row + e);
        r = __shfl_sync(0xffffffffu, r, lane & 16);
        float4 v = __ldg(attr4 + idx);
        float* dst = combined + (size_t)r * CDIM + HID + g * 4;
        asm volatile("red.global.add.v4.f32 [%0], {%1, %2, %3, %4};"
                     :: "l"(dst), "f"(v.x), "f"(v.y), "f"(v.z), "f"(v.w)
                     : "memory");
        idx += stride;
    }
    // tail: at most one partial-warp iteration
    if (idx < end) {
        int e = (int)(idx >> 4);
        int r = __ldg(row + e);
        float4 v = __ldg(attr4 + idx);
        float* dst = combined + (size_t)r * CDIM + HID + g * 4;
        asm volatile("red.global.add.v4.f32 [%0], {%1, %2, %3, %4};"
                     :: "l"(dst), "f"(v.x), "f"(v.y), "f"(v.z), "f"(v.w)
                     : "memory");
    }
}

// ---------------------------------------------------------------------------
// K1: fused scatter + t1-GEMM (+ combined[:,0:64] = x copy).
// Blocks [0, SCAT_BLOCKS) scatter; blocks [SCAT_BLOCKS, TOTAL) do the
// x @ W1a GEMM on the fma pipe (overlapping the scatter's LSU/REDG work),
// then help finish the scatter tail.
// ---------------------------------------------------------------------------
__global__ void scatter_gemm_kernel(const int* __restrict__ row,
                                    const float4* __restrict__ attr4,
                                    const float4* __restrict__ x4,
                                    const float* __restrict__ W1,
                                    const float* __restrict__ b1,
                                    float* __restrict__ combined) {
    int tid = threadIdx.x;

    if (blockIdx.x < SCAT_BLOCKS) {
        long long idx0 = (long long)blockIdx.x * 256 + tid;
        scatter_range(row, attr4, combined, 0, SPLIT_ITEMS,
                      idx0, (long long)SCAT_BLOCKS * 256);
        return;
    }

    // ---- GEMM branch: t1 = x @ W1[0:64,:] + b1 ----
    extern __shared__ float4 smem4[];
    float*  sW  = (float*)smem4;                 // 64*64 floats (16 KB)
    float4* sx4 = smem4 + (HID * HID) / 4;       // 32 nodes * 16 float4 (8 KB)

    for (int i = tid; i < HID * HID; i += 256) sW[i] = W1[i];
    float bj = __ldg(b1 + (tid & 63));
    __syncthreads();

    int g = tid >> 6;          // group 0..3
    int j = tid & 63;          // output feature
    int bid = blockIdx.x - SCAT_BLOCKS;
    float4* comb4 = (float4*)combined;

    for (int tile = bid; tile < N_TILES; tile += GEMM_BLOCKS) {
        int node0 = tile * NTILE;

        // stage x rows into smem; also emit combined[:,0:64] = x
        for (int i = tid; i < NTILE * 16; i += 256) {
            int n = node0 + (i >> 4), q = i & 15;
            float4 v = make_float4(0.f, 0.f, 0.f, 0.f);
            if (n < N_NODES) {
                v = __ldg(x4 + (size_t)n * 16 + q);
                comb4[(size_t)n * 32 + q] = v;
            }
            sx4[i] = v;
        }
        __syncthreads();

        float acc[8];
        #pragma unroll
        for (int n = 0; n < 8; n++) acc[n] = bj;

        const float4* c0 = sx4 + g * 8 * 16;
        #pragma unroll 4
        for (int i4 = 0; i4 < 16; i4++) {
            float w0 = sW[(i4 * 4 + 0) * HID + j];
            float w1 = sW[(i4 * 4 + 1) * HID + j];
            float w2 = sW[(i4 * 4 + 2) * HID + j];
            float w3 = sW[(i4 * 4 + 3) * HID + j];
            #pragma unroll
            for (int n = 0; n < 8; n++) {
                float4 c = c0[n * 16 + i4];
                acc[n] = fmaf(c.x, w0, acc[n]);
                acc[n] = fmaf(c.y, w1, acc[n]);
                acc[n] = fmaf(c.z, w2, acc[n]);
                acc[n] = fmaf(c.w, w3, acc[n]);
            }
        }
        #pragma unroll
        for (int n = 0; n < 8; n++) {
            int node = node0 + g * 8 + n;
            if (node < N_NODES) d_t1[(size_t)node * HID + j] = acc[n];
        }
        __syncthreads();
    }

    // ---- help finish the scatter tail ----
    long long idx0 = (long long)bid * 256 + tid;
    scatter_range(row, attr4, combined, SPLIT_ITEMS, TOTAL_ITEMS,
                  idx0, (long long)GEMM_BLOCKS * 256);
}

// ---------------------------------------------------------------------------
// K2: out = silu(t1 + agg @ W1[64:128,:]) @ W2 + b2
// 8-node register blocking + float4 smem loads.
// ---------------------------------------------------------------------------
__global__ void mlp2_kernel(const float* __restrict__ combined,
                            const float* __restrict__ W1,
                            const float* __restrict__ W2,
                            const float* __restrict__ b2,
                            float* __restrict__ out) {
    extern __shared__ float4 smem4[];
    float*  sW1b  = (float*)smem4;                     // 64*64 (16 KB)
    float*  sW2   = sW1b + HID * HID;                  // 64*64 (16 KB)
    float4* sagg4 = (float4*)(sW2 + HID * HID);        // 32*16 float4 (8 KB)
    float4* sh4   = sagg4 + NTILE * 16;                // 32*16 float4 (8 KB)
    float*  sh    = (float*)sh4;

    int tid = threadIdx.x;
    for (int i = tid; i < HID * HID; i += 256) sW1b[i] = W1[HID * HID + i];
    for (int i = tid; i < HID * HID; i += 256) sW2[i]  = W2[i];
    float b2j = __ldg(b2 + (tid & 63));
    __syncthreads();

    int g = tid >> 6;
    int j = tid & 63;
    const float4* comb4 = (const float4*)combined;

    for (int tile = blockIdx.x; tile < N_TILES; tile += gridDim.x) {
        int node0 = tile * NTILE;

        for (int i = tid; i < NTILE * 16; i += 256) {
            int n = node0 + (i >> 4), q = i & 15;
            sagg4[i] = (n < N_NODES)
                         ? __ldg(comb4 + (size_t)n * 32 + 16 + q)
                         : make_float4(0.f, 0.f, 0.f, 0.f);
        }
        __syncthreads();

        float acc[8];
        #pragma unroll
        for (int n = 0; n < 8; n++) {
            int node = node0 + g * 8 + n;
            acc[n] = (node < N_NODES) ? d_t1[(size_t)node * HID + j] : 0.f;
        }
        const float4* c0 = sagg4 + g * 8 * 16;
        #pragma unroll 4
        for (int k4 = 0; k4 < 16; k4++) {
            float w0 = sW1b[(k4 * 4 + 0) * HID + j];
            float w1 = sW1b[(k4 * 4 + 1) * HID + j];
            float w2 = sW1b[(k4 * 4 + 2) * HID + j];
            float w3 = sW1b[(k4 * 4 + 3) * HID + j];
            #pragma unroll
            for (int n = 0; n < 8; n++) {
                float4 c = c0[n * 16 + k4];
                acc[n] = fmaf(c.x, w0, acc[n]);
                acc[n] = fmaf(c.y, w1, acc[n]);
                acc[n] = fmaf(c.z, w2, acc[n]);
                acc[n] = fmaf(c.w, w3, acc[n]);
            }
        }
        #pragma unroll
        for (int n = 0; n < 8; n++) {
            float a = acc[n];
            sh[(g * 8 + n) * HID + j] = a / (1.0f + __expf(-a));
        }
        __syncthreads();

        float acc2[8];
        #pragma unroll
        for (int n = 0; n < 8; n++) acc2[n] = b2j;
        const float4* h0 = sh4 + g * 8 * 16;
        #pragma unroll 4
        for (int k4 = 0; k4 < 16; k4++) {
            float w0 = sW2[(k4 * 4 + 0) * HID + j];
            float w1 = sW2[(k4 * 4 + 1) * HID + j];
            float w2 = sW2[(k4 * 4 + 2) * HID + j];
            float w3 = sW2[(k4 * 4 + 3) * HID + j];
            #pragma unroll
            for (int n = 0; n < 8; n++) {
                float4 c = h0[n * 16 + k4];
                acc2[n] = fmaf(c.x, w0, acc2[n]);
                acc2[n] = fmaf(c.y, w1, acc2[n]);
                acc2[n] = fmaf(c.z, w2, acc2[n]);
                acc2[n] = fmaf(c.w, w3, acc2[n]);
            }
        }
        #pragma unroll
        for (int n = 0; n < 8; n++) {
            int node = node0 + g * 8 + n;
            if (node < N_NODES) out[(size_t)node * HID + j] = acc2[n];
        }
        __syncthreads();
    }
}

// ---------------------------------------------------------------------------
extern "C" void kernel_launch(void* const* d_in, const int* in_sizes, int n_in,
                              void* d_out, int out_size) {
    const int*   edge_index = (const int*)d_in[0];   // [2, N_EDGES]; row = first half
    const float* edge_attr  = (const float*)d_in[1]; // [N_EDGES, 64]
    const float* x          = (const float*)d_in[2]; // [N_NODES, 64]
    const float* W1         = (const float*)d_in[3]; // [128, 64]
    const float* b1         = (const float*)d_in[4]; // [64]
    const float* W2         = (const float*)d_in[5]; // [64, 64]
    const float* b2         = (const float*)d_in[6]; // [64]

    float* out      = (float*)d_out;                 // [N_NODES, 64]
    float* combined = out + (size_t)N_NODES * HID;   // [N_NODES, 128]

    // K0: zero the combined region (x-half overwritten by K1's GEMM branch).
    // DMA memset, no SM kernel, graph-capturable.
    cudaMemsetAsync(combined, 0, (size_t)N_NODES * CDIM * sizeof(float));

    // K1: scatter + t1 GEMM + x copy
    {
        int smem = (HID * HID) * 4 + NTILE * 16 * 16;   // 16 KB + 8 KB
        cudaFuncSetAttribute(scatter_gemm_kernel,
                             cudaFuncAttributeMaxDynamicSharedMemorySize, smem);
        scatter_gemm_kernel<<<TOTAL_BLOCKS, 256, smem>>>(
            edge_index, (const float4*)edge_attr, (const float4*)x,
            W1, b1, combined);
    }

    // K2: remaining MLP
    {
        int smem = 2 * (HID * HID) * 4 + 2 * NTILE * 16 * 16;  // 48 KB
        cudaFuncSetAttribute(mlp2_kernel,
                             cudaFuncAttributeMaxDynamicSharedMemorySize, smem);
        mlp2_kernel<<<592, 256, smem>>>(combined, W1, W2, b2, out);
    }
}